// round 2
// baseline (speedup 1.0000x reference)
#include <cuda_runtime.h>
#include <cuda_bf16.h>

#define NB 4
#define CH 512
#define HW 4096
#define NG 32
#define CPG 16

// Scratch (static device globals: allocation-free per harness rules)
static __device__ float g_h[NB * CH * HW];                 // 33.5 MB groupnorm output
static __device__ float g_q[NB * CH * HW];
static __device__ float g_k[NB * CH * HW];
static __device__ float g_v[NB * CH * HW];
static __device__ float g_o[NB * CH * HW];
static __device__ float g_s[(size_t)NB * HW * HW];         // 268 MB scores/attn

// ---------------------------------------------------------------------------
// GroupNorm: one block per (batch, group). 16 ch x 4096 = 65536 elems/group.
// ---------------------------------------------------------------------------
__global__ __launch_bounds__(512) void groupnorm_kernel(
    const float* __restrict__ x, const float* __restrict__ gamma,
    const float* __restrict__ beta, float* __restrict__ out)
{
    int b = blockIdx.x / NG, g = blockIdx.x % NG;
    size_t base = ((size_t)b * CH + (size_t)g * CPG) * HW;
    const float4* x4 = (const float4*)(x + base);
    const int n4 = CPG * HW / 4;  // 16384 float4s

    float s = 0.f, ss = 0.f;
    for (int i = threadIdx.x; i < n4; i += blockDim.x) {
        float4 v = x4[i];
        s  += v.x + v.y + v.z + v.w;
        ss += v.x * v.x + v.y * v.y + v.z * v.z + v.w * v.w;
    }
    __shared__ float shs[16], shss[16];
#pragma unroll
    for (int o = 16; o > 0; o >>= 1) {
        s  += __shfl_xor_sync(0xffffffffu, s, o);
        ss += __shfl_xor_sync(0xffffffffu, ss, o);
    }
    int wid = threadIdx.x >> 5, lid = threadIdx.x & 31;
    if (lid == 0) { shs[wid] = s; shss[wid] = ss; }
    __syncthreads();
    if (threadIdx.x == 0) {
        float ts = 0.f, tss = 0.f;
#pragma unroll
        for (int w = 0; w < 16; w++) { ts += shs[w]; tss += shss[w]; }
        shs[0] = ts; shss[0] = tss;
    }
    __syncthreads();
    const float invn = 1.f / (float)(CPG * HW);
    float mean = shs[0] * invn;
    float var  = shss[0] * invn - mean * mean;
    float rstd = rsqrtf(var + 1e-5f);

    float4* o4 = (float4*)(out + base);
    for (int i = threadIdx.x; i < n4; i += blockDim.x) {
        int ch = g * CPG + (i >> 10);  // i*4/4096
        float ga = gamma[ch] * rstd;
        float be = beta[ch] - mean * ga;
        float4 v = x4[i];
        v.x = v.x * ga + be; v.y = v.y * ga + be;
        v.z = v.z * ga + be; v.w = v.w * ga + be;
        o4[i] = v;
    }
}

// ---------------------------------------------------------------------------
// GEMM NN: C[b][m][n] = A[m][k] * B[b][k][n] + bias[m] (+ resid). M=512,N=4096,K=512
// 128x128 tile, BK=8, 256 threads, 8x8 per thread. Next-tile register prefetch.
// ---------------------------------------------------------------------------
__global__ __launch_bounds__(256) void gemm_nn(
    const float* __restrict__ A, const float* __restrict__ Bbase,
    const float* __restrict__ bias, const float* __restrict__ Rbase,
    float* __restrict__ Cbase)
{
    const int K = CH, N = HW;
    __shared__ float As[8][132];  // padded: scattered transpose writes
    __shared__ float Bs[8][128];
    size_t boff = (size_t)blockIdx.z * CH * HW;
    const float* Bp = Bbase + boff;
    float* Cp = Cbase + boff;
    int row0 = blockIdx.y * 128, col0 = blockIdx.x * 128;
    int tid = threadIdx.x;
    int tx = tid & 15, ty = tid >> 4;
    int aRow = tid >> 1, aK = (tid & 1) << 2;
    int bK = tid >> 5, bCol = (tid & 31) << 2;
    float acc[8][8] = {};

    const float* aPtr = A + (size_t)(row0 + aRow) * K + aK;
    const float* bPtr = Bp + (size_t)bK * N + col0 + bCol;
    float4 av = *(const float4*)aPtr;
    float4 bv = *(const float4*)bPtr;

    for (int k0 = 0; k0 < K; k0 += 8) {
        As[aK + 0][aRow] = av.x; As[aK + 1][aRow] = av.y;
        As[aK + 2][aRow] = av.z; As[aK + 3][aRow] = av.w;
        *(float4*)&Bs[bK][bCol] = bv;
        __syncthreads();
        if (k0 + 8 < K) {
            av = *(const float4*)(aPtr + k0 + 8);
            bv = *(const float4*)(bPtr + (size_t)(k0 + 8) * N);
        }
#pragma unroll
        for (int k = 0; k < 8; k++) {
            float ra[8], rb[8];
#pragma unroll
            for (int i = 0; i < 8; i++) ra[i] = As[k][ty * 8 + i];
#pragma unroll
            for (int j = 0; j < 8; j++) rb[j] = Bs[k][tx * 8 + j];
#pragma unroll
            for (int i = 0; i < 8; i++)
#pragma unroll
                for (int j = 0; j < 8; j++) acc[i][j] = fmaf(ra[i], rb[j], acc[i][j]);
        }
        __syncthreads();
    }
#pragma unroll
    for (int i = 0; i < 8; i++) {
        int r = row0 + ty * 8 + i;
        float bi = bias[r];
        size_t rowoff = (size_t)r * N + col0 + tx * 8;
#pragma unroll
        for (int j4 = 0; j4 < 8; j4 += 4) {
            float4 v;
            v.x = acc[i][j4 + 0] + bi; v.y = acc[i][j4 + 1] + bi;
            v.z = acc[i][j4 + 2] + bi; v.w = acc[i][j4 + 3] + bi;
            if (Rbase) {
                float4 rv = *(const float4*)(Rbase + boff + rowoff + j4);
                v.x += rv.x; v.y += rv.y; v.z += rv.z; v.w += rv.w;
            }
            *(float4*)(Cp + rowoff + j4) = v;
        }
    }
}

// ---------------------------------------------------------------------------
// Scores (TN): S[b][n][m] = scale * sum_c Q[b][c][n] * K[b][c][m]
// Both operands K-major (row=c, contiguous spatial) -> direct coalesced tiles.
// M=N=4096, K=512. Next-tile register prefetch.
// ---------------------------------------------------------------------------
__global__ __launch_bounds__(256) void gemm_tn_scores(
    const float* __restrict__ Qb, const float* __restrict__ Kb,
    float* __restrict__ Sb)
{
    __shared__ float As[8][128];
    __shared__ float Bs[8][128];
    size_t qoff = (size_t)blockIdx.z * CH * HW;
    const float* Qp = Qb + qoff;
    const float* Kp = Kb + qoff;
    float* Sp = Sb + (size_t)blockIdx.z * HW * HW;
    int row0 = blockIdx.y * 128, col0 = blockIdx.x * 128;
    int tid = threadIdx.x, tx = tid & 15, ty = tid >> 4;
    int lK = tid >> 5, lC = (tid & 31) << 2;
    float acc[8][8] = {};

    const float* qPtr = Qp + (size_t)lK * HW + row0 + lC;
    const float* kPtr = Kp + (size_t)lK * HW + col0 + lC;
    float4 av = *(const float4*)qPtr;
    float4 bv = *(const float4*)kPtr;

    for (int k0 = 0; k0 < CH; k0 += 8) {
        *(float4*)&As[lK][lC] = av;
        *(float4*)&Bs[lK][lC] = bv;
        __syncthreads();
        if (k0 + 8 < CH) {
            av = *(const float4*)(qPtr + (size_t)(k0 + 8) * HW);
            bv = *(const float4*)(kPtr + (size_t)(k0 + 8) * HW);
        }
#pragma unroll
        for (int k = 0; k < 8; k++) {
            float ra[8], rb[8];
#pragma unroll
            for (int i = 0; i < 8; i++) ra[i] = As[k][ty * 8 + i];
#pragma unroll
            for (int j = 0; j < 8; j++) rb[j] = Bs[k][tx * 8 + j];
#pragma unroll
            for (int i = 0; i < 8; i++)
#pragma unroll
                for (int j = 0; j < 8; j++) acc[i][j] = fmaf(ra[i], rb[j], acc[i][j]);
        }
        __syncthreads();
    }
    const float scale = 0.04419417382415922f;  // 512^-0.5
#pragma unroll
    for (int i = 0; i < 8; i++) {
        size_t ro = (size_t)(row0 + ty * 8 + i) * HW + col0 + tx * 8;
#pragma unroll
        for (int j4 = 0; j4 < 8; j4 += 4) {
            float4 v;
            v.x = acc[i][j4 + 0] * scale; v.y = acc[i][j4 + 1] * scale;
            v.z = acc[i][j4 + 2] * scale; v.w = acc[i][j4 + 3] * scale;
            *(float4*)(Sp + ro + j4) = v;
        }
    }
}

// ---------------------------------------------------------------------------
// Row softmax in place over last dim (4096). One block per row.
// ---------------------------------------------------------------------------
__global__ __launch_bounds__(256) void softmax_kernel(float* __restrict__ S)
{
    float4* p4 = (float4*)(S + (size_t)blockIdx.x * HW);
    int tid = threadIdx.x;
    float4 r[4];
    float mx = -3.0e38f;
#pragma unroll
    for (int i = 0; i < 4; i++) {
        r[i] = p4[tid + i * 256];
        mx = fmaxf(mx, fmaxf(fmaxf(r[i].x, r[i].y), fmaxf(r[i].z, r[i].w)));
    }
    __shared__ float red[8];
#pragma unroll
    for (int o = 16; o > 0; o >>= 1) mx = fmaxf(mx, __shfl_xor_sync(0xffffffffu, mx, o));
    if ((tid & 31) == 0) red[tid >> 5] = mx;
    __syncthreads();
    mx = red[0];
#pragma unroll
    for (int w = 1; w < 8; w++) mx = fmaxf(mx, red[w]);

    float sum = 0.f;
#pragma unroll
    for (int i = 0; i < 4; i++) {
        r[i].x = __expf(r[i].x - mx); r[i].y = __expf(r[i].y - mx);
        r[i].z = __expf(r[i].z - mx); r[i].w = __expf(r[i].w - mx);
        sum += r[i].x + r[i].y + r[i].z + r[i].w;
    }
#pragma unroll
    for (int o = 16; o > 0; o >>= 1) sum += __shfl_xor_sync(0xffffffffu, sum, o);
    __syncthreads();
    if ((tid & 31) == 0) red[tid >> 5] = sum;
    __syncthreads();
    sum = 0.f;
#pragma unroll
    for (int w = 0; w < 8; w++) sum += red[w];
    float inv = 1.f / sum;
#pragma unroll
    for (int i = 0; i < 4; i++) {
        r[i].x *= inv; r[i].y *= inv; r[i].z *= inv; r[i].w *= inv;
        p4[tid + i * 256] = r[i];
    }
}

// ---------------------------------------------------------------------------
// Out (NT): O[b][c][n] = sum_m V[b][c][m] * Attn[b][n][m]. M=512,N=4096,K=4096.
// Both operands K-contiguous -> load with transpose into smem. Prefetched.
// ---------------------------------------------------------------------------
__global__ __launch_bounds__(256) void gemm_nt_out(
    const float* __restrict__ Vb, const float* __restrict__ Sb,
    float* __restrict__ Ob)
{
    __shared__ float As[8][132];
    __shared__ float Bs[8][132];
    size_t voff = (size_t)blockIdx.z * CH * HW;
    const float* Vp = Vb + voff;
    const float* Ap = Sb + (size_t)blockIdx.z * HW * HW;
    float* Op = Ob + voff;
    int row0 = blockIdx.y * 128, col0 = blockIdx.x * 128;
    int tid = threadIdx.x, tx = tid & 15, ty = tid >> 4;
    int mRow = tid >> 1, mK = (tid & 1) << 2;
    float acc[8][8] = {};

    const float* vPtr = Vp + (size_t)(row0 + mRow) * HW + mK;
    const float* sPtr = Ap + (size_t)(col0 + mRow) * HW + mK;
    float4 av = *(const float4*)vPtr;
    float4 bv = *(const float4*)sPtr;

    for (int k0 = 0; k0 < HW; k0 += 8) {
        As[mK + 0][mRow] = av.x; As[mK + 1][mRow] = av.y;
        As[mK + 2][mRow] = av.z; As[mK + 3][mRow] = av.w;
        Bs[mK + 0][mRow] = bv.x; Bs[mK + 1][mRow] = bv.y;
        Bs[mK + 2][mRow] = bv.z; Bs[mK + 3][mRow] = bv.w;
        __syncthreads();
        if (k0 + 8 < HW) {
            av = *(const float4*)(vPtr + k0 + 8);
            bv = *(const float4*)(sPtr + k0 + 8);
        }
#pragma unroll
        for (int k = 0; k < 8; k++) {
            float ra[8], rb[8];
#pragma unroll
            for (int i = 0; i < 8; i++) ra[i] = As[k][ty * 8 + i];
#pragma unroll
            for (int j = 0; j < 8; j++) rb[j] = Bs[k][tx * 8 + j];
#pragma unroll
            for (int i = 0; i < 8; i++)
#pragma unroll
                for (int j = 0; j < 8; j++) acc[i][j] = fmaf(ra[i], rb[j], acc[i][j]);
        }
        __syncthreads();
    }
#pragma unroll
    for (int i = 0; i < 8; i++) {
        size_t ro = (size_t)(row0 + ty * 8 + i) * HW + col0 + tx * 8;
#pragma unroll
        for (int j4 = 0; j4 < 8; j4 += 4) {
            float4 v;
            v.x = acc[i][j4 + 0]; v.y = acc[i][j4 + 1];
            v.z = acc[i][j4 + 2]; v.w = acc[i][j4 + 3];
            *(float4*)(Op + ro + j4) = v;
        }
    }
}

// ---------------------------------------------------------------------------
extern "C" void kernel_launch(void* const* d_in, const int* in_sizes, int n_in,
                              void* d_out, int out_size)
{
    const float* x     = (const float*)d_in[0];
    const float* gamma = (const float*)d_in[1];
    const float* beta  = (const float*)d_in[2];
    const float* wq    = (const float*)d_in[3];
    const float* bq    = (const float*)d_in[4];
    const float* wk    = (const float*)d_in[5];
    const float* bk    = (const float*)d_in[6];
    const float* wv    = (const float*)d_in[7];
    const float* bv    = (const float*)d_in[8];
    const float* wo    = (const float*)d_in[9];
    const float* bo    = (const float*)d_in[10];
    float* out = (float*)d_out;

    float *ph, *pq, *pk, *pv, *po, *ps;
    cudaGetSymbolAddress((void**)&ph, g_h);
    cudaGetSymbolAddress((void**)&pq, g_q);
    cudaGetSymbolAddress((void**)&pk, g_k);
    cudaGetSymbolAddress((void**)&pv, g_v);
    cudaGetSymbolAddress((void**)&po, g_o);
    cudaGetSymbolAddress((void**)&ps, g_s);

    groupnorm_kernel<<<NB * NG, 512>>>(x, gamma, beta, ph);

    dim3 gp(HW / 128, CH / 128, NB);   // 32 x 4 x 4
    gemm_nn<<<gp, 256>>>(wq, ph, bq, nullptr, pq);
    gemm_nn<<<gp, 256>>>(wk, ph, bk, nullptr, pk);
    gemm_nn<<<gp, 256>>>(wv, ph, bv, nullptr, pv);

    dim3 gs(HW / 128, HW / 128, NB);   // 32 x 32 x 4
    gemm_tn_scores<<<gs, 256>>>(pq, pk, ps);

    softmax_kernel<<<NB * HW, 256>>>(ps);

    gemm_nt_out<<<gp, 256>>>(pv, ps, po);

    gemm_nn<<<gp, 256>>>(wo, po, bo, x, out);
}

// round 3
// speedup vs baseline: 2.5663x; 2.5663x over previous
#include <cuda_runtime.h>
#include <cuda_bf16.h>
#include <cstdint>

#define NB 4
#define CH 512
#define HW 4096
#define NG 32
#define CPG 16
#define CHW ((long long)CH * HW)   // 2097152
#define SS  ((long long)HW * HW)   // 16777216

// Scratch (static device globals: allocation-free per harness rules)
static __device__ float g_ht[NB * CH * HW];                // H^T  [n][c]
static __device__ float g_q [NB * CH * HW];                // Q^T  [n][c]
static __device__ float g_k [NB * CH * HW];                // K^T  [m][c]
static __device__ float g_v [NB * CH * HW];                // V    [c][m]
static __device__ float g_o [NB * CH * HW];                // O^T  [n][c]
static __device__ float g_s [(size_t)NB * HW * HW];        // S    [n][m]

// ---------------------------------------------------------------------------
// helpers
// ---------------------------------------------------------------------------
__device__ __forceinline__ uint32_t f2tf(float f) {
    uint32_t r;
    asm("cvt.rna.tf32.f32 %0, %1;" : "=r"(r) : "f"(f));
    return r;
}

__device__ __forceinline__ void mma8(float* c, const uint32_t* a, const uint32_t* b) {
    asm volatile(
        "mma.sync.aligned.m16n8k8.row.col.f32.tf32.tf32.f32 "
        "{%0,%1,%2,%3}, {%4,%5,%6,%7}, {%8,%9}, {%0,%1,%2,%3};"
        : "+f"(c[0]), "+f"(c[1]), "+f"(c[2]), "+f"(c[3])
        : "r"(a[0]), "r"(a[1]), "r"(a[2]), "r"(a[3]), "r"(b[0]), "r"(b[1]));
}

// ---------------------------------------------------------------------------
// GroupNorm -> transposed output H^T[n][c].
// One block per (batch, group): 16 ch x 4096 positions.
// ---------------------------------------------------------------------------
__global__ __launch_bounds__(512) void groupnorm_t_kernel(
    const float* __restrict__ x, const float* __restrict__ gamma,
    const float* __restrict__ beta, float* __restrict__ ht)
{
    int b = blockIdx.x / NG, grp = blockIdx.x % NG;
    size_t base = ((size_t)b * CH + (size_t)grp * CPG) * HW;
    const float4* x4 = (const float4*)(x + base);
    const int n4 = CPG * HW / 4;  // 16384

    float s = 0.f, ss = 0.f;
    for (int i = threadIdx.x; i < n4; i += blockDim.x) {
        float4 v = x4[i];
        s  += v.x + v.y + v.z + v.w;
        ss += v.x * v.x + v.y * v.y + v.z * v.z + v.w * v.w;
    }
    __shared__ float shs[16], shss[16];
#pragma unroll
    for (int o = 16; o > 0; o >>= 1) {
        s  += __shfl_xor_sync(0xffffffffu, s, o);
        ss += __shfl_xor_sync(0xffffffffu, ss, o);
    }
    int wid = threadIdx.x >> 5, lid = threadIdx.x & 31;
    if (lid == 0) { shs[wid] = s; shss[wid] = ss; }
    __syncthreads();
    if (threadIdx.x == 0) {
        float ts = 0.f, tss = 0.f;
#pragma unroll
        for (int w = 0; w < 16; w++) { ts += shs[w]; tss += shss[w]; }
        shs[0] = ts; shss[0] = tss;
    }
    __syncthreads();
    const float invn = 1.f / (float)(CPG * HW);
    float mean = shs[0] * invn;
    float var  = shss[0] * invn - mean * mean;
    float rstd = rsqrtf(var + 1e-5f);

    // per-thread channel for the load phase
    int ch  = threadIdx.x >> 5;        // 0..15
    int nl  = threadIdx.x & 31;        // 0..31 (float4 index within 128-n tile)
    float ga = gamma[grp * CPG + ch] * rstd;
    float be = beta [grp * CPG + ch] - mean * ga;

    __shared__ float sm[16 * 132];
    float* htp = ht + (size_t)b * CHW;

    for (int tile = 0; tile < HW / 128; tile++) {
        float4 v = x4[ch * (HW / 4) + tile * 32 + nl];
        v.x = v.x * ga + be; v.y = v.y * ga + be;
        v.z = v.z * ga + be; v.w = v.w * ga + be;
        *(float4*)&sm[ch * 132 + nl * 4] = v;
        __syncthreads();
        // write H^T[n][c]: 128 n x 16 c, thread -> (i = n-local, c4)
        int i  = threadIdx.x >> 2;     // 0..127
        int c4 = threadIdx.x & 3;      // 0..3
        float4 w;
        w.x = sm[(c4 * 4 + 0) * 132 + i];
        w.y = sm[(c4 * 4 + 1) * 132 + i];
        w.z = sm[(c4 * 4 + 2) * 132 + i];
        w.w = sm[(c4 * 4 + 3) * 132 + i];
        *(float4*)(htp + (size_t)(tile * 128 + i) * CH + grp * CPG + c4 * 4) = w;
        __syncthreads();
    }
}

// ---------------------------------------------------------------------------
// Unified tf32 mma GEMM.
//   C[m][n] = sum_k A[m][k] * B[n][k]   (both operands k-contiguous)
//   128x128 block tile, BK=32, 256 threads (8 warps as 2x4 of 64x32 tiles).
//   TRANS: write C transposed as CT[n][m].  BIAS: + bias[m].  RESID: + resid.
// ---------------------------------------------------------------------------
template<bool TRANS, bool HASBIAS, bool HASRESID>
__global__ __launch_bounds__(256) void mma_gemm(
    const float* __restrict__ A, int ldA, long long aStride,
    const float* __restrict__ B, int ldB, long long bStride,
    float* __restrict__ C, int ldC, long long cStride,
    const float* __restrict__ bias,
    const float* __restrict__ resid, long long rStride,
    int K, float scale)
{
    __shared__ uint32_t As[128 * 36];
    __shared__ uint32_t Bs[128 * 36];

    const int tid  = threadIdx.x;
    const int lane = tid & 31;
    const int wid  = tid >> 5;
    const int g    = lane >> 2;       // 0..7
    const int t    = lane & 3;        // 0..3
    const int warpM = (wid >> 2) * 64;
    const int warpN = (wid & 3) * 32;

    const int m0 = blockIdx.y * 128, n0 = blockIdx.x * 128;
    const float* Ap = A + blockIdx.z * aStride;
    const float* Bp = B + blockIdx.z * bStride;

    // loader mapping: thread covers rows r0 + {0,32,64,96}, fixed kq
    const int r0 = tid >> 3;          // 0..31
    const int kq = tid & 7;           // float4 column within BK=32

    float acc[4][4][4] = {};
    float4 sa[4], sb[4];

#pragma unroll
    for (int i = 0; i < 4; i++) {
        sa[i] = *(const float4*)(Ap + (size_t)(m0 + r0 + 32 * i) * ldA + kq * 4);
        sb[i] = *(const float4*)(Bp + (size_t)(n0 + r0 + 32 * i) * ldB + kq * 4);
    }

    for (int k0 = 0; k0 < K; k0 += 32) {
#pragma unroll
        for (int i = 0; i < 4; i++) {
            int w = (r0 + 32 * i) * 36 + kq * 4;
            As[w + 0] = f2tf(sa[i].x); As[w + 1] = f2tf(sa[i].y);
            As[w + 2] = f2tf(sa[i].z); As[w + 3] = f2tf(sa[i].w);
            Bs[w + 0] = f2tf(sb[i].x); Bs[w + 1] = f2tf(sb[i].y);
            Bs[w + 2] = f2tf(sb[i].z); Bs[w + 3] = f2tf(sb[i].w);
        }
        __syncthreads();
        if (k0 + 32 < K) {
#pragma unroll
            for (int i = 0; i < 4; i++) {
                sa[i] = *(const float4*)(Ap + (size_t)(m0 + r0 + 32 * i) * ldA + k0 + 32 + kq * 4);
                sb[i] = *(const float4*)(Bp + (size_t)(n0 + r0 + 32 * i) * ldB + k0 + 32 + kq * 4);
            }
        }
#pragma unroll
        for (int kk = 0; kk < 4; kk++) {
            const int kb = kk * 8;
            uint32_t af[4][4], bf[4][2];
#pragma unroll
            for (int mt = 0; mt < 4; mt++) {
                int r = warpM + mt * 16 + g;
                af[mt][0] = As[(r)     * 36 + kb + t];
                af[mt][1] = As[(r + 8) * 36 + kb + t];
                af[mt][2] = As[(r)     * 36 + kb + t + 4];
                af[mt][3] = As[(r + 8) * 36 + kb + t + 4];
            }
#pragma unroll
            for (int nt = 0; nt < 4; nt++) {
                int r = warpN + nt * 8 + g;
                bf[nt][0] = Bs[r * 36 + kb + t];
                bf[nt][1] = Bs[r * 36 + kb + t + 4];
            }
#pragma unroll
            for (int mt = 0; mt < 4; mt++)
#pragma unroll
                for (int nt = 0; nt < 4; nt++)
                    mma8(acc[mt][nt], af[mt], bf[nt]);
        }
        __syncthreads();
    }

    // epilogue
    float* Cp = C + blockIdx.z * cStride;
    const float* Rp = HASRESID ? (resid + blockIdx.z * rStride) : nullptr;
#pragma unroll
    for (int mt = 0; mt < 4; mt++) {
        int row = m0 + warpM + mt * 16 + g;
        float b0 = 0.f, b1 = 0.f;
        if (HASBIAS) { b0 = bias[row]; b1 = bias[row + 8]; }
#pragma unroll
        for (int nt = 0; nt < 4; nt++) {
            int col = n0 + warpN + nt * 8 + 2 * t;
            float v0 = acc[mt][nt][0] * scale + b0;
            float v1 = acc[mt][nt][1] * scale + b0;
            float v2 = acc[mt][nt][2] * scale + b1;
            float v3 = acc[mt][nt][3] * scale + b1;
            if (TRANS) {
                Cp[(size_t)(col)     * ldC + row    ] = v0;
                Cp[(size_t)(col + 1) * ldC + row    ] = v1;
                Cp[(size_t)(col)     * ldC + row + 8] = v2;
                Cp[(size_t)(col + 1) * ldC + row + 8] = v3;
            } else {
                if (HASRESID) {
                    float2 r0v = *(const float2*)(Rp + (size_t)row * ldC + col);
                    float2 r1v = *(const float2*)(Rp + (size_t)(row + 8) * ldC + col);
                    v0 += r0v.x; v1 += r0v.y; v2 += r1v.x; v3 += r1v.y;
                }
                *(float2*)(Cp + (size_t)row * ldC + col)       = make_float2(v0, v1);
                *(float2*)(Cp + (size_t)(row + 8) * ldC + col) = make_float2(v2, v3);
            }
        }
    }
}

// ---------------------------------------------------------------------------
// Row softmax in place over last dim (4096). One block per row.
// ---------------------------------------------------------------------------
__global__ __launch_bounds__(256) void softmax_kernel(float* __restrict__ S)
{
    float4* p4 = (float4*)(S + (size_t)blockIdx.x * HW);
    int tid = threadIdx.x;
    float4 r[4];
    float mx = -3.0e38f;
#pragma unroll
    for (int i = 0; i < 4; i++) {
        r[i] = p4[tid + i * 256];
        mx = fmaxf(mx, fmaxf(fmaxf(r[i].x, r[i].y), fmaxf(r[i].z, r[i].w)));
    }
    __shared__ float red[8];
#pragma unroll
    for (int o = 16; o > 0; o >>= 1) mx = fmaxf(mx, __shfl_xor_sync(0xffffffffu, mx, o));
    if ((tid & 31) == 0) red[tid >> 5] = mx;
    __syncthreads();
    mx = red[0];
#pragma unroll
    for (int w = 1; w < 8; w++) mx = fmaxf(mx, red[w]);

    float sum = 0.f;
#pragma unroll
    for (int i = 0; i < 4; i++) {
        r[i].x = __expf(r[i].x - mx); r[i].y = __expf(r[i].y - mx);
        r[i].z = __expf(r[i].z - mx); r[i].w = __expf(r[i].w - mx);
        sum += r[i].x + r[i].y + r[i].z + r[i].w;
    }
#pragma unroll
    for (int o = 16; o > 0; o >>= 1) sum += __shfl_xor_sync(0xffffffffu, sum, o);
    __syncthreads();
    if ((tid & 31) == 0) red[tid >> 5] = sum;
    __syncthreads();
    sum = 0.f;
#pragma unroll
    for (int w = 0; w < 8; w++) sum += red[w];
    float inv = 1.f / sum;
#pragma unroll
    for (int i = 0; i < 4; i++) {
        r[i].x *= inv; r[i].y *= inv; r[i].z *= inv; r[i].w *= inv;
        p4[tid + i * 256] = r[i];
    }
}

// ---------------------------------------------------------------------------
extern "C" void kernel_launch(void* const* d_in, const int* in_sizes, int n_in,
                              void* d_out, int out_size)
{
    const float* x     = (const float*)d_in[0];
    const float* gamma = (const float*)d_in[1];
    const float* beta  = (const float*)d_in[2];
    const float* wq    = (const float*)d_in[3];
    const float* bq    = (const float*)d_in[4];
    const float* wk    = (const float*)d_in[5];
    const float* bk    = (const float*)d_in[6];
    const float* wv    = (const float*)d_in[7];
    const float* bv    = (const float*)d_in[8];
    const float* wo    = (const float*)d_in[9];
    const float* bo    = (const float*)d_in[10];
    float* out = (float*)d_out;

    float *pht, *pq, *pk, *pv, *po, *ps;
    cudaGetSymbolAddress((void**)&pht, g_ht);
    cudaGetSymbolAddress((void**)&pq,  g_q);
    cudaGetSymbolAddress((void**)&pk,  g_k);
    cudaGetSymbolAddress((void**)&pv,  g_v);
    cudaGetSymbolAddress((void**)&po,  g_o);
    cudaGetSymbolAddress((void**)&ps,  g_s);

    // GroupNorm -> H^T[n][c]
    groupnorm_t_kernel<<<NB * NG, 512>>>(x, gamma, beta, pht);

    dim3 gP(HW / 128, CH / 128, NB);   // 32 x 4 x 4 (proj GEMMs: M=512, N=4096)
    dim3 gS(HW / 128, HW / 128, NB);   // 32 x 32 x 4 (scores: M=N=4096)

    // Q^T = (Wq . H)^T   [n][d], transposed epilogue
    mma_gemm<true, true, false><<<gP, 256>>>(wq, CH, 0, pht, CH, CHW,
                                             pq, CH, CHW, bq, nullptr, 0, CH, 1.f);
    // K^T
    mma_gemm<true, true, false><<<gP, 256>>>(wk, CH, 0, pht, CH, CHW,
                                             pk, CH, CHW, bk, nullptr, 0, CH, 1.f);
    // V natural [d][n]
    mma_gemm<false, true, false><<<gP, 256>>>(wv, CH, 0, pht, CH, CHW,
                                              pv, HW, CHW, bv, nullptr, 0, CH, 1.f);
    // S[n][m] = scale * Q^T . K^T^T  (A = Q^T rows n, B = K^T rows m, k = c)
    mma_gemm<false, false, false><<<gS, 256>>>(pq, CH, CHW, pk, CH, CHW,
                                               ps, HW, SS, nullptr, nullptr, 0,
                                               CH, 0.04419417382415922f);
    softmax_kernel<<<NB * HW, 256>>>(ps);

    // O^T[n][c]: A = V[c][m] (M=512 rows c), B = attn[n][m], k = m; transposed write
    mma_gemm<true, false, false><<<gP, 256>>>(pv, HW, CHW, ps, HW, SS,
                                              po, CH, CHW, nullptr, nullptr, 0, HW, 1.f);
    // out[d][n] = Wo . O + bo + x : A = Wo[d][c], B = O^T[n][c], k = c
    mma_gemm<false, true, true><<<gP, 256>>>(wo, CH, 0, po, CH, CHW,
                                             out, HW, CHW, bo, x, CHW, CH, 1.f);
}

// round 4
// speedup vs baseline: 3.2091x; 1.2504x over previous
#include <cuda_runtime.h>
#include <cuda_bf16.h>
#include <cstdint>

#define NB 4
#define CH 512
#define HW 4096
#define NG 32
#define CPG 16
#define CHW ((long long)CH * HW)   // 2097152
#define SS  ((long long)HW * HW)   // 16777216

// smem geometry (uint32 units): 128 rows x (32 k + 4 pad)
#define SM_STRIDE 36
#define SM_OP     (128 * SM_STRIDE)       // 4608 u32 per operand
#define SM_STAGE  (2 * SM_OP)             // A + B per stage
#define SMEM_BYTES (2 * SM_STAGE * 4)     // 73728 B, double buffered

// Scratch (static device globals: allocation-free per harness rules)
static __device__ float g_ht[NB * CH * HW];                // H^T  [n][c]
static __device__ float g_q [NB * CH * HW];                // Q^T  [n][c]
static __device__ float g_k [NB * CH * HW];                // K^T  [m][c]
static __device__ float g_v [NB * CH * HW];                // V    [c][m]
static __device__ float g_o [NB * CH * HW];                // O^T  [n][c]
static __device__ float g_s [(size_t)NB * HW * HW];        // S    [n][m]

// ---------------------------------------------------------------------------
// helpers
// ---------------------------------------------------------------------------
__device__ __forceinline__ void mma8(float* c, const uint32_t* a, const uint32_t* b) {
    asm volatile(
        "mma.sync.aligned.m16n8k8.row.col.f32.tf32.tf32.f32 "
        "{%0,%1,%2,%3}, {%4,%5,%6,%7}, {%8,%9}, {%0,%1,%2,%3};"
        : "+f"(c[0]), "+f"(c[1]), "+f"(c[2]), "+f"(c[3])
        : "r"(a[0]), "r"(a[1]), "r"(a[2]), "r"(a[3]), "r"(b[0]), "r"(b[1]));
}

__device__ __forceinline__ void cpasync16(uint32_t dst, const void* src) {
    asm volatile("cp.async.cg.shared.global [%0], [%1], 16;" :: "r"(dst), "l"(src));
}

__device__ __forceinline__ uint32_t smem_u32(const void* p) {
    uint32_t a;
    asm("{ .reg .u64 t; cvta.to.shared.u64 t, %1; cvt.u32.u64 %0, t; }" : "=r"(a) : "l"(p));
    return a;
}

// ---------------------------------------------------------------------------
// GroupNorm -> transposed output H^T[n][c].
// ---------------------------------------------------------------------------
__global__ __launch_bounds__(512) void groupnorm_t_kernel(
    const float* __restrict__ x, const float* __restrict__ gamma,
    const float* __restrict__ beta, float* __restrict__ ht)
{
    int b = blockIdx.x / NG, grp = blockIdx.x % NG;
    size_t base = ((size_t)b * CH + (size_t)grp * CPG) * HW;
    const float4* x4 = (const float4*)(x + base);
    const int n4 = CPG * HW / 4;  // 16384

    float s = 0.f, ss = 0.f;
    for (int i = threadIdx.x; i < n4; i += blockDim.x) {
        float4 v = x4[i];
        s  += v.x + v.y + v.z + v.w;
        ss += v.x * v.x + v.y * v.y + v.z * v.z + v.w * v.w;
    }
    __shared__ float shs[16], shss[16];
#pragma unroll
    for (int o = 16; o > 0; o >>= 1) {
        s  += __shfl_xor_sync(0xffffffffu, s, o);
        ss += __shfl_xor_sync(0xffffffffu, ss, o);
    }
    int wid = threadIdx.x >> 5, lid = threadIdx.x & 31;
    if (lid == 0) { shs[wid] = s; shss[wid] = ss; }
    __syncthreads();
    if (threadIdx.x == 0) {
        float ts = 0.f, tss = 0.f;
#pragma unroll
        for (int w = 0; w < 16; w++) { ts += shs[w]; tss += shss[w]; }
        shs[0] = ts; shss[0] = tss;
    }
    __syncthreads();
    const float invn = 1.f / (float)(CPG * HW);
    float mean = shs[0] * invn;
    float var  = shss[0] * invn - mean * mean;
    float rstd = rsqrtf(var + 1e-5f);

    int ch  = threadIdx.x >> 5;        // 0..15
    int nl  = threadIdx.x & 31;        // 0..31
    float ga = gamma[grp * CPG + ch] * rstd;
    float be = beta [grp * CPG + ch] - mean * ga;

    __shared__ float sm[16 * 132];
    float* htp = ht + (size_t)b * CHW;

    for (int tile = 0; tile < HW / 128; tile++) {
        float4 v = x4[ch * (HW / 4) + tile * 32 + nl];
        v.x = v.x * ga + be; v.y = v.y * ga + be;
        v.z = v.z * ga + be; v.w = v.w * ga + be;
        *(float4*)&sm[ch * 132 + nl * 4] = v;
        __syncthreads();
        int i  = threadIdx.x >> 2;     // 0..127
        int c4 = threadIdx.x & 3;      // 0..3
        float4 w;
        w.x = sm[(c4 * 4 + 0) * 132 + i];
        w.y = sm[(c4 * 4 + 1) * 132 + i];
        w.z = sm[(c4 * 4 + 2) * 132 + i];
        w.w = sm[(c4 * 4 + 3) * 132 + i];
        *(float4*)(htp + (size_t)(tile * 128 + i) * CH + grp * CPG + c4 * 4) = w;
        __syncthreads();
    }
}

// ---------------------------------------------------------------------------
// Unified tf32 mma GEMM, cp.async double-buffered.
//   C[m][n] = sum_k A[m][k] * B[n][k]   (both operands k-contiguous)
//   128x128 tile, BK=32, 256 threads (8 warps, 64x32 warp tiles).
// ---------------------------------------------------------------------------
template<bool TRANS, bool HASBIAS, bool HASRESID>
__global__ __launch_bounds__(256, 2) void mma_gemm(
    const float* __restrict__ A, int ldA, long long aStride,
    const float* __restrict__ B, int ldB, long long bStride,
    float* __restrict__ C, int ldC, long long cStride,
    const float* __restrict__ bias,
    const float* __restrict__ resid, long long rStride,
    int K, float scale)
{
    extern __shared__ uint32_t sm[];
    const uint32_t smb = smem_u32(sm);

    const int tid  = threadIdx.x;
    const int lane = tid & 31;
    const int wid  = tid >> 5;
    const int g    = lane >> 2;       // 0..7
    const int t    = lane & 3;        // 0..3
    const int warpM = (wid >> 2) * 64;
    const int warpN = (wid & 3) * 32;

    const int m0 = blockIdx.y * 128, n0 = blockIdx.x * 128;
    const float* Ap = A + blockIdx.z * aStride;
    const float* Bp = B + blockIdx.z * bStride;

    // loader mapping: thread covers rows r0 + {0,32,64,96}, fixed 16B column kq
    const int r0 = tid >> 3;          // 0..31
    const int kq = tid & 7;           // float4 col within BK=32

    float acc[4][4][4] = {};

    // issue one stage of cp.async (8 x 16B per thread)
    auto load_stage = [&](int st, int k0) {
        uint32_t dA = smb + (uint32_t)(st * SM_STAGE + r0 * SM_STRIDE + kq * 4) * 4;
        uint32_t dB = dA + SM_OP * 4;
        const float* sA = Ap + (size_t)(m0 + r0) * ldA + k0 + kq * 4;
        const float* sB = Bp + (size_t)(n0 + r0) * ldB + k0 + kq * 4;
#pragma unroll
        for (int i = 0; i < 4; i++) {
            cpasync16(dA + (uint32_t)(32 * i * SM_STRIDE) * 4, sA + (size_t)(32 * i) * ldA);
            cpasync16(dB + (uint32_t)(32 * i * SM_STRIDE) * 4, sB + (size_t)(32 * i) * ldB);
        }
    };

    load_stage(0, 0);
    asm volatile("cp.async.commit_group;");

    int s = 0;
    for (int k0 = 0; k0 < K; k0 += 32, s ^= 1) {
        if (k0 + 32 < K) {
            load_stage(s ^ 1, k0 + 32);
            asm volatile("cp.async.commit_group;");
            asm volatile("cp.async.wait_group 1;");
        } else {
            asm volatile("cp.async.wait_group 0;");
        }
        __syncthreads();

        const uint32_t* As = sm + s * SM_STAGE;
        const uint32_t* Bs = As + SM_OP;
#pragma unroll
        for (int kk = 0; kk < 4; kk++) {
            const int kb = kk * 8;
            uint32_t af[4][4], bf[4][2];
#pragma unroll
            for (int mt = 0; mt < 4; mt++) {
                int r = warpM + mt * 16 + g;
                af[mt][0] = As[(r)     * SM_STRIDE + kb + t];
                af[mt][1] = As[(r + 8) * SM_STRIDE + kb + t];
                af[mt][2] = As[(r)     * SM_STRIDE + kb + t + 4];
                af[mt][3] = As[(r + 8) * SM_STRIDE + kb + t + 4];
            }
#pragma unroll
            for (int nt = 0; nt < 4; nt++) {
                int r = warpN + nt * 8 + g;
                bf[nt][0] = Bs[r * SM_STRIDE + kb + t];
                bf[nt][1] = Bs[r * SM_STRIDE + kb + t + 4];
            }
#pragma unroll
            for (int mt = 0; mt < 4; mt++)
#pragma unroll
                for (int nt = 0; nt < 4; nt++)
                    mma8(acc[mt][nt], af[mt], bf[nt]);
        }
        __syncthreads();
    }

    // epilogue
    float* Cp = C + blockIdx.z * cStride;
    const float* Rp = HASRESID ? (resid + blockIdx.z * rStride) : nullptr;
#pragma unroll
    for (int mt = 0; mt < 4; mt++) {
        int row = m0 + warpM + mt * 16 + g;
        float b0 = 0.f, b1 = 0.f;
        if (HASBIAS) { b0 = bias[row]; b1 = bias[row + 8]; }
#pragma unroll
        for (int nt = 0; nt < 4; nt++) {
            int col = n0 + warpN + nt * 8 + 2 * t;
            float v0 = acc[mt][nt][0] * scale + b0;
            float v1 = acc[mt][nt][1] * scale + b0;
            float v2 = acc[mt][nt][2] * scale + b1;
            float v3 = acc[mt][nt][3] * scale + b1;
            if (TRANS) {
                Cp[(size_t)(col)     * ldC + row    ] = v0;
                Cp[(size_t)(col + 1) * ldC + row    ] = v1;
                Cp[(size_t)(col)     * ldC + row + 8] = v2;
                Cp[(size_t)(col + 1) * ldC + row + 8] = v3;
            } else {
                if (HASRESID) {
                    float2 r0v = *(const float2*)(Rp + (size_t)row * ldC + col);
                    float2 r1v = *(const float2*)(Rp + (size_t)(row + 8) * ldC + col);
                    v0 += r0v.x; v1 += r0v.y; v2 += r1v.x; v3 += r1v.y;
                }
                *(float2*)(Cp + (size_t)row * ldC + col)       = make_float2(v0, v1);
                *(float2*)(Cp + (size_t)(row + 8) * ldC + col) = make_float2(v2, v3);
            }
        }
    }
}

// ---------------------------------------------------------------------------
// Row softmax in place over last dim (4096). One block per row.
// ---------------------------------------------------------------------------
__global__ __launch_bounds__(256) void softmax_kernel(float* __restrict__ S)
{
    float4* p4 = (float4*)(S + (size_t)blockIdx.x * HW);
    int tid = threadIdx.x;
    float4 r[4];
    float mx = -3.0e38f;
#pragma unroll
    for (int i = 0; i < 4; i++) {
        r[i] = p4[tid + i * 256];
        mx = fmaxf(mx, fmaxf(fmaxf(r[i].x, r[i].y), fmaxf(r[i].z, r[i].w)));
    }
    __shared__ float red[8];
#pragma unroll
    for (int o = 16; o > 0; o >>= 1) mx = fmaxf(mx, __shfl_xor_sync(0xffffffffu, mx, o));
    if ((tid & 31) == 0) red[tid >> 5] = mx;
    __syncthreads();
    mx = red[0];
#pragma unroll
    for (int w = 1; w < 8; w++) mx = fmaxf(mx, red[w]);

    float sum = 0.f;
#pragma unroll
    for (int i = 0; i < 4; i++) {
        r[i].x = __expf(r[i].x - mx); r[i].y = __expf(r[i].y - mx);
        r[i].z = __expf(r[i].z - mx); r[i].w = __expf(r[i].w - mx);
        sum += r[i].x + r[i].y + r[i].z + r[i].w;
    }
#pragma unroll
    for (int o = 16; o > 0; o >>= 1) sum += __shfl_xor_sync(0xffffffffu, sum, o);
    __syncthreads();
    if ((tid & 31) == 0) red[tid >> 5] = sum;
    __syncthreads();
    sum = 0.f;
#pragma unroll
    for (int w = 0; w < 8; w++) sum += red[w];
    float inv = 1.f / sum;
#pragma unroll
    for (int i = 0; i < 4; i++) {
        r[i].x *= inv; r[i].y *= inv; r[i].z *= inv; r[i].w *= inv;
        p4[tid + i * 256] = r[i];
    }
}

// ---------------------------------------------------------------------------
extern "C" void kernel_launch(void* const* d_in, const int* in_sizes, int n_in,
                              void* d_out, int out_size)
{
    const float* x     = (const float*)d_in[0];
    const float* gamma = (const float*)d_in[1];
    const float* beta  = (const float*)d_in[2];
    const float* wq    = (const float*)d_in[3];
    const float* bq    = (const float*)d_in[4];
    const float* wk    = (const float*)d_in[5];
    const float* bk    = (const float*)d_in[6];
    const float* wv    = (const float*)d_in[7];
    const float* bv    = (const float*)d_in[8];
    const float* wo    = (const float*)d_in[9];
    const float* bo    = (const float*)d_in[10];
    float* out = (float*)d_out;

    float *pht, *pq, *pk, *pv, *po, *ps;
    cudaGetSymbolAddress((void**)&pht, g_ht);
    cudaGetSymbolAddress((void**)&pq,  g_q);
    cudaGetSymbolAddress((void**)&pk,  g_k);
    cudaGetSymbolAddress((void**)&pv,  g_v);
    cudaGetSymbolAddress((void**)&po,  g_o);
    cudaGetSymbolAddress((void**)&ps,  g_s);

    // opt-in to >48KB dynamic smem (idempotent; host-side, graph-safe)
    cudaFuncSetAttribute(mma_gemm<true,  true,  false>, cudaFuncAttributeMaxDynamicSharedMemorySize, SMEM_BYTES);
    cudaFuncSetAttribute(mma_gemm<false, true,  false>, cudaFuncAttributeMaxDynamicSharedMemorySize, SMEM_BYTES);
    cudaFuncSetAttribute(mma_gemm<false, false, false>, cudaFuncAttributeMaxDynamicSharedMemorySize, SMEM_BYTES);
    cudaFuncSetAttribute(mma_gemm<true,  false, false>, cudaFuncAttributeMaxDynamicSharedMemorySize, SMEM_BYTES);
    cudaFuncSetAttribute(mma_gemm<false, true,  true >, cudaFuncAttributeMaxDynamicSharedMemorySize, SMEM_BYTES);

    // GroupNorm -> H^T[n][c]
    groupnorm_t_kernel<<<NB * NG, 512>>>(x, gamma, beta, pht);

    dim3 gP(HW / 128, CH / 128, NB);   // proj GEMMs: M=512, N=4096
    dim3 gS(HW / 128, HW / 128, NB);   // scores: M=N=4096

    // Q^T = (Wq . H)^T, transposed epilogue
    mma_gemm<true, true, false><<<gP, 256, SMEM_BYTES>>>(wq, CH, 0, pht, CH, CHW,
                                             pq, CH, CHW, bq, nullptr, 0, CH, 1.f);
    // K^T
    mma_gemm<true, true, false><<<gP, 256, SMEM_BYTES>>>(wk, CH, 0, pht, CH, CHW,
                                             pk, CH, CHW, bk, nullptr, 0, CH, 1.f);
    // V natural [d][n]
    mma_gemm<false, true, false><<<gP, 256, SMEM_BYTES>>>(wv, CH, 0, pht, CH, CHW,
                                              pv, HW, CHW, bv, nullptr, 0, CH, 1.f);
    // S[n][m] = scale * Q . K^T  (A = Q^T rows n, B = K^T rows m, k = c)
    mma_gemm<false, false, false><<<gS, 256, SMEM_BYTES>>>(pq, CH, CHW, pk, CH, CHW,
                                               ps, HW, SS, nullptr, nullptr, 0,
                                               CH, 0.04419417382415922f);
    softmax_kernel<<<NB * HW, 256>>>(ps);

    // O^T[n][c]: A = V[c][m], B = attn[n][m], k = m; transposed write
    mma_gemm<true, false, false><<<gP, 256, SMEM_BYTES>>>(pv, HW, CHW, ps, HW, SS,
                                              po, CH, CHW, nullptr, nullptr, 0, HW, 1.f);
    // out[d][n] = Wo . O + bo + x
    mma_gemm<false, true, true><<<gP, 256, SMEM_BYTES>>>(wo, CH, 0, po, CH, CHW,
                                             out, HW, CHW, bo, x, CHW, CH, 1.f);
}

// round 5
// speedup vs baseline: 3.5250x; 1.0985x over previous
#include <cuda_runtime.h>
#include <cuda_bf16.h>
#include <cstdint>

#define NB 4
#define CH 512
#define HW 4096
#define NG 32
#define CPG 16
#define CHW ((long long)CH * HW)   // 2097152
#define SS  ((long long)HW * HW)   // 16777216

// smem geometry (uint32 units): 128 rows x (32 k + 8 pad) -> stride 40
// stride 40 => conflict-free LDS.64 frag loads (banks 8g+2t) and cp.async stores
#define SM_STRIDE 40
#define SM_OP     (128 * SM_STRIDE)       // 5120 u32 per operand
#define SM_STAGE  (2 * SM_OP)             // A + B per stage
#define SMEM_BYTES (2 * SM_STAGE * 4)     // 81920 B, double buffered

// Scratch (static device globals: allocation-free per harness rules)
static __device__ float g_ht[NB * CH * HW];                // H^T  [n][c]
static __device__ float g_q [NB * CH * HW];                // Q^T  [n][c]
static __device__ float g_k [NB * CH * HW];                // K^T  [m][c]
static __device__ float g_v [NB * CH * HW];                // V    [c][m]
static __device__ float g_o [NB * CH * HW];                // O^T  [n][c]
static __device__ float g_s [(size_t)NB * HW * HW];        // S    [n][m]

// ---------------------------------------------------------------------------
// helpers
// ---------------------------------------------------------------------------
__device__ __forceinline__ void mma8(float* c, const uint32_t* a, const uint32_t* b) {
    asm volatile(
        "mma.sync.aligned.m16n8k8.row.col.f32.tf32.tf32.f32 "
        "{%0,%1,%2,%3}, {%4,%5,%6,%7}, {%8,%9}, {%0,%1,%2,%3};"
        : "+f"(c[0]), "+f"(c[1]), "+f"(c[2]), "+f"(c[3])
        : "r"(a[0]), "r"(a[1]), "r"(a[2]), "r"(a[3]), "r"(b[0]), "r"(b[1]));
}

__device__ __forceinline__ void cpasync16(uint32_t dst, const void* src) {
    asm volatile("cp.async.cg.shared.global [%0], [%1], 16;" :: "r"(dst), "l"(src));
}

__device__ __forceinline__ uint32_t smem_u32(const void* p) {
    uint32_t a;
    asm("{ .reg .u64 t; cvta.to.shared.u64 t, %1; cvt.u32.u64 %0, t; }" : "=r"(a) : "l"(p));
    return a;
}

// ---------------------------------------------------------------------------
// GroupNorm -> transposed output H^T[n][c].
// ---------------------------------------------------------------------------
__global__ __launch_bounds__(512) void groupnorm_t_kernel(
    const float* __restrict__ x, const float* __restrict__ gamma,
    const float* __restrict__ beta, float* __restrict__ ht)
{
    int b = blockIdx.x / NG, grp = blockIdx.x % NG;
    size_t base = ((size_t)b * CH + (size_t)grp * CPG) * HW;
    const float4* x4 = (const float4*)(x + base);
    const int n4 = CPG * HW / 4;  // 16384

    float s = 0.f, ss = 0.f;
    for (int i = threadIdx.x; i < n4; i += blockDim.x) {
        float4 v = x4[i];
        s  += v.x + v.y + v.z + v.w;
        ss += v.x * v.x + v.y * v.y + v.z * v.z + v.w * v.w;
    }
    __shared__ float shs[16], shss[16];
#pragma unroll
    for (int o = 16; o > 0; o >>= 1) {
        s  += __shfl_xor_sync(0xffffffffu, s, o);
        ss += __shfl_xor_sync(0xffffffffu, ss, o);
    }
    int wid = threadIdx.x >> 5, lid = threadIdx.x & 31;
    if (lid == 0) { shs[wid] = s; shss[wid] = ss; }
    __syncthreads();
    if (threadIdx.x == 0) {
        float ts = 0.f, tss = 0.f;
#pragma unroll
        for (int w = 0; w < 16; w++) { ts += shs[w]; tss += shss[w]; }
        shs[0] = ts; shss[0] = tss;
    }
    __syncthreads();
    const float invn = 1.f / (float)(CPG * HW);
    float mean = shs[0] * invn;
    float var  = shss[0] * invn - mean * mean;
    float rstd = rsqrtf(var + 1e-5f);

    int ch  = threadIdx.x >> 5;        // 0..15
    int nl  = threadIdx.x & 31;        // 0..31
    float ga = gamma[grp * CPG + ch] * rstd;
    float be = beta [grp * CPG + ch] - mean * ga;

    __shared__ float sm[16 * 132];
    float* htp = ht + (size_t)b * CHW;

    for (int tile = 0; tile < HW / 128; tile++) {
        float4 v = x4[ch * (HW / 4) + tile * 32 + nl];
        v.x = v.x * ga + be; v.y = v.y * ga + be;
        v.z = v.z * ga + be; v.w = v.w * ga + be;
        *(float4*)&sm[ch * 132 + nl * 4] = v;
        __syncthreads();
        int i  = threadIdx.x >> 2;     // 0..127
        int c4 = threadIdx.x & 3;      // 0..3
        float4 w;
        w.x = sm[(c4 * 4 + 0) * 132 + i];
        w.y = sm[(c4 * 4 + 1) * 132 + i];
        w.z = sm[(c4 * 4 + 2) * 132 + i];
        w.w = sm[(c4 * 4 + 3) * 132 + i];
        *(float4*)(htp + (size_t)(tile * 128 + i) * CH + grp * CPG + c4 * 4) = w;
        __syncthreads();
    }
}

// ---------------------------------------------------------------------------
// Unified tf32 mma GEMM, cp.async double-buffered, LDS.64 fragment loads.
//   C[m][n] = sum_k A[m][k] * B[n][k]   (both operands k-contiguous)
//   128x128 tile, BK=32, 256 threads (8 warps, 64x32 warp tiles).
//   k-permutation: logical klo(t)=kb+2t, khi(t)=kb+2t+1 (same for A & B ->
//   MMA result invariant; enables 8B-vectorized fragment loads).
// ---------------------------------------------------------------------------
template<bool TRANS, bool HASBIAS, bool HASRESID>
__global__ __launch_bounds__(256, 2) void mma_gemm(
    const float* __restrict__ A, int ldA, long long aStride,
    const float* __restrict__ B, int ldB, long long bStride,
    float* __restrict__ C, int ldC, long long cStride,
    const float* __restrict__ bias,
    const float* __restrict__ resid, long long rStride,
    int K, float scale)
{
    extern __shared__ uint32_t sm[];
    const uint32_t smb = smem_u32(sm);

    const int tid  = threadIdx.x;
    const int lane = tid & 31;
    const int wid  = tid >> 5;
    const int g    = lane >> 2;       // 0..7
    const int t    = lane & 3;        // 0..3
    const int warpM = (wid >> 2) * 64;
    const int warpN = (wid & 3) * 32;

    const int m0 = blockIdx.y * 128, n0 = blockIdx.x * 128;
    const float* Ap = A + blockIdx.z * aStride;
    const float* Bp = B + blockIdx.z * bStride;

    // loader mapping: thread covers rows r0 + {0,32,64,96}, fixed 16B col kq
    const int r0 = tid >> 3;          // 0..31
    const int kq = tid & 7;           // float4 col within BK=32

    float acc[4][4][4] = {};

    auto load_stage = [&](int st, int k0) {
        uint32_t dA = smb + (uint32_t)(st * SM_STAGE + r0 * SM_STRIDE + kq * 4) * 4;
        uint32_t dB = dA + SM_OP * 4;
        const float* sA = Ap + (size_t)(m0 + r0) * ldA + k0 + kq * 4;
        const float* sB = Bp + (size_t)(n0 + r0) * ldB + k0 + kq * 4;
#pragma unroll
        for (int i = 0; i < 4; i++) {
            cpasync16(dA + (uint32_t)(32 * i * SM_STRIDE) * 4, sA + (size_t)(32 * i) * ldA);
            cpasync16(dB + (uint32_t)(32 * i * SM_STRIDE) * 4, sB + (size_t)(32 * i) * ldB);
        }
    };

    load_stage(0, 0);
    asm volatile("cp.async.commit_group;");

    int s = 0;
    for (int k0 = 0; k0 < K; k0 += 32, s ^= 1) {
        if (k0 + 32 < K) {
            load_stage(s ^ 1, k0 + 32);
            asm volatile("cp.async.commit_group;");
            asm volatile("cp.async.wait_group 1;");
        } else {
            asm volatile("cp.async.wait_group 0;");
        }
        __syncthreads();

        const uint32_t* As = sm + s * SM_STAGE;
        const uint32_t* Bs = As + SM_OP;
#pragma unroll
        for (int kk = 0; kk < 4; kk++) {
            const int kc = kk * 8 + 2 * t;       // klo column; khi = kc+1
            uint32_t af[4][4], bf[4][2];
#pragma unroll
            for (int mt = 0; mt < 4; mt++) {
                int r = warpM + mt * 16 + g;
                uint2 lo = *(const uint2*)&As[(r)     * SM_STRIDE + kc];
                uint2 hi = *(const uint2*)&As[(r + 8) * SM_STRIDE + kc];
                af[mt][0] = lo.x; af[mt][1] = hi.x;
                af[mt][2] = lo.y; af[mt][3] = hi.y;
            }
#pragma unroll
            for (int nt = 0; nt < 4; nt++) {
                int r = warpN + nt * 8 + g;
                uint2 bb = *(const uint2*)&Bs[r * SM_STRIDE + kc];
                bf[nt][0] = bb.x; bf[nt][1] = bb.y;
            }
#pragma unroll
            for (int mt = 0; mt < 4; mt++)
#pragma unroll
                for (int nt = 0; nt < 4; nt++)
                    mma8(acc[mt][nt], af[mt], bf[nt]);
        }
        __syncthreads();
    }

    // epilogue
    float* Cp = C + blockIdx.z * cStride;
    const float* Rp = HASRESID ? (resid + blockIdx.z * rStride) : nullptr;
#pragma unroll
    for (int mt = 0; mt < 4; mt++) {
        int row = m0 + warpM + mt * 16 + g;
        float b0 = 0.f, b1 = 0.f;
        if (HASBIAS) { b0 = bias[row]; b1 = bias[row + 8]; }
#pragma unroll
        for (int nt = 0; nt < 4; nt++) {
            int col = n0 + warpN + nt * 8 + 2 * t;
            float v0 = acc[mt][nt][0] * scale + b0;
            float v1 = acc[mt][nt][1] * scale + b0;
            float v2 = acc[mt][nt][2] * scale + b1;
            float v3 = acc[mt][nt][3] * scale + b1;
            if (TRANS) {
                Cp[(size_t)(col)     * ldC + row    ] = v0;
                Cp[(size_t)(col + 1) * ldC + row    ] = v1;
                Cp[(size_t)(col)     * ldC + row + 8] = v2;
                Cp[(size_t)(col + 1) * ldC + row + 8] = v3;
            } else {
                if (HASRESID) {
                    float2 r0v = *(const float2*)(Rp + (size_t)row * ldC + col);
                    float2 r1v = *(const float2*)(Rp + (size_t)(row + 8) * ldC + col);
                    v0 += r0v.x; v1 += r0v.y; v2 += r1v.x; v3 += r1v.y;
                }
                *(float2*)(Cp + (size_t)row * ldC + col)       = make_float2(v0, v1);
                *(float2*)(Cp + (size_t)(row + 8) * ldC + col) = make_float2(v2, v3);
            }
        }
    }
}

// ---------------------------------------------------------------------------
// Row softmax in place over last dim (4096). One block per row.
// ---------------------------------------------------------------------------
__global__ __launch_bounds__(256) void softmax_kernel(float* __restrict__ S)
{
    float4* p4 = (float4*)(S + (size_t)blockIdx.x * HW);
    int tid = threadIdx.x;
    float4 r[4];
    float mx = -3.0e38f;
#pragma unroll
    for (int i = 0; i < 4; i++) {
        r[i] = p4[tid + i * 256];
        mx = fmaxf(mx, fmaxf(fmaxf(r[i].x, r[i].y), fmaxf(r[i].z, r[i].w)));
    }
    __shared__ float red[8];
#pragma unroll
    for (int o = 16; o > 0; o >>= 1) mx = fmaxf(mx, __shfl_xor_sync(0xffffffffu, mx, o));
    if ((tid & 31) == 0) red[tid >> 5] = mx;
    __syncthreads();
    mx = red[0];
#pragma unroll
    for (int w = 1; w < 8; w++) mx = fmaxf(mx, red[w]);

    float sum = 0.f;
#pragma unroll
    for (int i = 0; i < 4; i++) {
        r[i].x = __expf(r[i].x - mx); r[i].y = __expf(r[i].y - mx);
        r[i].z = __expf(r[i].z - mx); r[i].w = __expf(r[i].w - mx);
        sum += r[i].x + r[i].y + r[i].z + r[i].w;
    }
#pragma unroll
    for (int o = 16; o > 0; o >>= 1) sum += __shfl_xor_sync(0xffffffffu, sum, o);
    __syncthreads();
    if ((tid & 31) == 0) red[tid >> 5] = sum;
    __syncthreads();
    sum = 0.f;
#pragma unroll
    for (int w = 0; w < 8; w++) sum += red[w];
    float inv = 1.f / sum;
#pragma unroll
    for (int i = 0; i < 4; i++) {
        r[i].x *= inv; r[i].y *= inv; r[i].z *= inv; r[i].w *= inv;
        p4[tid + i * 256] = r[i];
    }
}

// ---------------------------------------------------------------------------
extern "C" void kernel_launch(void* const* d_in, const int* in_sizes, int n_in,
                              void* d_out, int out_size)
{
    const float* x     = (const float*)d_in[0];
    const float* gamma = (const float*)d_in[1];
    const float* beta  = (const float*)d_in[2];
    const float* wq    = (const float*)d_in[3];
    const float* bq    = (const float*)d_in[4];
    const float* wk    = (const float*)d_in[5];
    const float* bk    = (const float*)d_in[6];
    const float* wv    = (const float*)d_in[7];
    const float* bv    = (const float*)d_in[8];
    const float* wo    = (const float*)d_in[9];
    const float* bo    = (const float*)d_in[10];
    float* out = (float*)d_out;

    float *pht, *pq, *pk, *pv, *po, *ps;
    cudaGetSymbolAddress((void**)&pht, g_ht);
    cudaGetSymbolAddress((void**)&pq,  g_q);
    cudaGetSymbolAddress((void**)&pk,  g_k);
    cudaGetSymbolAddress((void**)&pv,  g_v);
    cudaGetSymbolAddress((void**)&po,  g_o);
    cudaGetSymbolAddress((void**)&ps,  g_s);

    cudaFuncSetAttribute(mma_gemm<true,  true,  false>, cudaFuncAttributeMaxDynamicSharedMemorySize, SMEM_BYTES);
    cudaFuncSetAttribute(mma_gemm<false, true,  false>, cudaFuncAttributeMaxDynamicSharedMemorySize, SMEM_BYTES);
    cudaFuncSetAttribute(mma_gemm<false, false, false>, cudaFuncAttributeMaxDynamicSharedMemorySize, SMEM_BYTES);
    cudaFuncSetAttribute(mma_gemm<true,  false, false>, cudaFuncAttributeMaxDynamicSharedMemorySize, SMEM_BYTES);
    cudaFuncSetAttribute(mma_gemm<false, true,  true >, cudaFuncAttributeMaxDynamicSharedMemorySize, SMEM_BYTES);

    // GroupNorm -> H^T[n][c]
    groupnorm_t_kernel<<<NB * NG, 512>>>(x, gamma, beta, pht);

    dim3 gP(HW / 128, CH / 128, NB);   // proj GEMMs: M=512, N=4096
    dim3 gS(HW / 128, HW / 128, NB);   // scores: M=N=4096

    // Q^T = (Wq . H)^T, transposed epilogue
    mma_gemm<true, true, false><<<gP, 256, SMEM_BYTES>>>(wq, CH, 0, pht, CH, CHW,
                                             pq, CH, CHW, bq, nullptr, 0, CH, 1.f);
    // K^T
    mma_gemm<true, true, false><<<gP, 256, SMEM_BYTES>>>(wk, CH, 0, pht, CH, CHW,
                                             pk, CH, CHW, bk, nullptr, 0, CH, 1.f);
    // V natural [d][n]
    mma_gemm<false, true, false><<<gP, 256, SMEM_BYTES>>>(wv, CH, 0, pht, CH, CHW,
                                              pv, HW, CHW, bv, nullptr, 0, CH, 1.f);
    // S[n][m] = scale * Q . K^T
    mma_gemm<false, false, false><<<gS, 256, SMEM_BYTES>>>(pq, CH, CHW, pk, CH, CHW,
                                               ps, HW, SS, nullptr, nullptr, 0,
                                               CH, 0.04419417382415922f);
    softmax_kernel<<<NB * HW, 256>>>(ps);

    // O^T[n][c]: A = V[c][m], B = attn[n][m], k = m; transposed write
    mma_gemm<true, false, false><<<gP, 256, SMEM_BYTES>>>(pv, HW, CHW, ps, HW, SS,
                                              po, CH, CHW, nullptr, nullptr, 0, HW, 1.f);
    // out[d][n] = Wo . O + bo + x
    mma_gemm<false, true, true><<<gP, 256, SMEM_BYTES>>>(wo, CH, 0, po, CH, CHW,
                                             out, HW, CHW, bo, x, CHW, CH, 1.f);
}